// round 12
// baseline (speedup 1.0000x reference)
#include <cuda_runtime.h>
#include <cstdint>

// Ragged position fill (vLLM prepare-inputs style).
//   pos[t]      = nct[idx_mapping[req(t)]] + (t - qsl[req(t)])   (= base + t)
//   seq_lens[r] = nct[idx_mapping[r]] + (qsl[r+1]-qsl[r]) for r<num_reqs, else 0
// d_out = [ pos (num_tokens) | seq_lens (max_num_reqs) ]  as FLOAT32.
//
// R12: five designs (STG small/large blocks, balanced tiles, persistent,
// TMA bulk) all plateau at 16.6-17.0us = 67MB @ 4.0 TB/s — the write-only
// HBM/L2-writeback ceiling. Structure: one (request, half) per block
// (simplest plateau design, 2-way split trims the straggler tail), with
// st.global.cs streaming stores so dirty-line writeback drains eagerly.

#define SEQ_BLOCKS 64
#define SPLIT 2

__device__ __forceinline__ void stg_cs_v4(float4* p, float a, float b,
                                          float c, float d) {
    asm volatile("st.global.cs.v4.f32 [%0], {%1, %2, %3, %4};"
                 :: "l"(p), "f"(a), "f"(b), "f"(c), "f"(d) : "memory");
}

__global__ __launch_bounds__(256) void fused_fill_kernel(
    const int* __restrict__ idx_mapping,
    const int* __restrict__ qsl,
    const int* __restrict__ nct,
    float* __restrict__ out_base,
    int num_reqs, int max_num_reqs,
    long long out_size)
{
    const int bid = (int)blockIdx.x;
    const int pos_blocks = num_reqs * SPLIT;

    if (bid >= pos_blocks) {
        // ---- seq_lens blocks: cover [0, max_num_reqs) ----
        const long long num_tokens = (long long)__ldg(&qsl[num_reqs]);
        const long long need = num_tokens + (long long)max_num_reqs;
        if (out_size != need && out_size != 4 * need) return;
        float* seq_out = out_base + num_tokens;
        const int nthreads = SEQ_BLOCKS * 256;
        int i = (bid - pos_blocks) * 256 + (int)threadIdx.x;
        for (; i < max_num_reqs; i += nthreads) {
            int v = 0;
            if (i < num_reqs) {
                int qlen = __ldg(&qsl[i + 1]) - __ldg(&qsl[i]);
                v = __ldg(&nct[__ldg(&idx_mapping[i])]) + qlen;
            }
            seq_out[i] = (float)v;
        }
        return;
    }

    // ---- pos blocks: request r, half h ----
    const int r = bid >> 1;
    const int h = bid & (SPLIT - 1);

    const int start = __ldg(&qsl[r]);
    const int end   = __ldg(&qsl[r + 1]);
    const int im    = __ldg(&idx_mapping[r]);
    if (end <= start) return;
    const int base  = __ldg(&nct[im]) - start;   // pos[t] = base + t

    // this block's half-range [s, e)
    const int half = ((end - start) + SPLIT - 1) / SPLIT;
    int s = start + h * half;
    int e = s + half;
    if (e > end) e = end;
    if (s >= e) return;

    const int a0 = (s + 3) & ~3;
    const int a1 = e & ~3;

    if (a1 > a0) {
        // head (<=3 elems)
        int t = s + (int)threadIdx.x;
        if (t < a0) out_base[t] = (float)(base + t);

        // body: streaming 16B stores of consecutive values
        const int nv4 = (a1 - a0) >> 2;
        float4* vp = reinterpret_cast<float4*>(out_base + a0);
        for (int v = (int)threadIdx.x; v < nv4; v += 256) {
            int tv = a0 + (v << 2) + base;
            stg_cs_v4(vp + v, (float)tv, (float)(tv + 1),
                      (float)(tv + 2), (float)(tv + 3));
        }

        // tail (<=3 elems)
        int tt = a1 + (int)threadIdx.x;
        if (tt < e) out_base[tt] = (float)(base + tt);
    } else {
        for (int t = s + (int)threadIdx.x; t < e; t += 256)
            out_base[t] = (float)(base + t);
    }
}

extern "C" void kernel_launch(void* const* d_in, const int* in_sizes, int n_in,
                              void* d_out, int out_size) {
    // stable sort of input indices by size (ascending)
    int ord[32];
    int n = n_in > 32 ? 32 : n_in;
    for (int i = 0; i < n; i++) ord[i] = i;
    for (int i = 1; i < n; i++) {
        int key = ord[i];
        int j = i - 1;
        while (j >= 0 && in_sizes[ord[j]] > in_sizes[key]) {
            ord[j + 1] = ord[j];
            j--;
        }
        ord[j + 1] = key;
    }
    // rank mapping: ord[0]=idx_mapping, ord[1]=qsl, ord[2]=num_computed_tokens
    int idx_i = ord[0];
    int qsl_i = (n > 1) ? ord[1] : ord[0];
    int nct_i = (n > 2) ? ord[2] : qsl_i;

    const int* idx_mapping = (const int*)d_in[idx_i];
    const int* qsl         = (const int*)d_in[qsl_i];
    const int* nct         = (const int*)d_in[nct_i];

    // unit: size(qsl) - size(idx) == bytes-per-element of in_sizes
    long long unit = (long long)in_sizes[qsl_i] - (long long)in_sizes[idx_i];
    if (unit <= 0) unit = 1;
    const int num_reqs     = (int)(in_sizes[idx_i] / unit);
    const int max_num_reqs = (int)(in_sizes[nct_i] / unit);

    fused_fill_kernel<<<num_reqs * SPLIT + SEQ_BLOCKS, 256>>>(
        idx_mapping, qsl, nct, (float*)d_out,
        num_reqs, max_num_reqs, (long long)out_size);
}

// round 13
// speedup vs baseline: 1.2429x; 1.2429x over previous
#include <cuda_runtime.h>
#include <cstdint>

// Ragged position fill (vLLM prepare-inputs style), single fused kernel.
//   pos[t]      = nct[idx_mapping[req(t)]] + (t - qsl[req(t)])   (= base + t)
//   seq_lens[r] = nct[idx_mapping[r]] + (qsl[r+1]-qsl[r]) for r < num_reqs, else 0
// d_out = [ pos (num_tokens) | seq_lens (max_num_reqs) ]  as FLOAT32.
//
// FINAL (revert to round-8 best): six structurally different designs
// (65K/8K/4K/1.2K blocks, STG and TMA-bulk, .cs and default policy) all
// plateau at 16.6-17.0us = 67MB at ~4 TB/s effective — the write-drain
// ceiling for this harness. This is the simplest design on that roofline:
// one block per request (256 thr), f32x2-incremented STG.128 bodies,
// dedicated blocks for seq_lens.

#define SEQ_BLOCKS 64

__device__ __forceinline__ unsigned long long addf32x2(unsigned long long a,
                                                       unsigned long long b) {
    unsigned long long r;
    asm("add.rn.f32x2 %0, %1, %2;" : "=l"(r) : "l"(a), "l"(b));
    return r;
}

__device__ __forceinline__ unsigned long long packf2(float lo, float hi) {
    unsigned long long r;
    asm("mov.b64 %0, {%1, %2};" : "=l"(r) : "f"(lo), "f"(hi));
    return r;
}

__global__ __launch_bounds__(256) void fused_fill_kernel(
    const int* __restrict__ idx_mapping,
    const int* __restrict__ qsl,
    const int* __restrict__ nct,
    float* __restrict__ out_base,
    int num_reqs, int max_num_reqs,
    long long out_size)
{
    const int r = blockIdx.x;

    if (r >= num_reqs) {
        // ---- seq_lens blocks: cover [0, max_num_reqs) ----
        const long long num_tokens = (long long)__ldg(&qsl[num_reqs]);
        const long long need = num_tokens + (long long)max_num_reqs;
        if (out_size != need && out_size != 4 * need) return;  // no room in d_out
        float* seq_out = out_base + num_tokens;

        const int nthreads = SEQ_BLOCKS * 256;
        int i = (r - num_reqs) * 256 + (int)threadIdx.x;
        for (; i < max_num_reqs; i += nthreads) {
            int v = 0;
            if (i < num_reqs) {
                int qlen = __ldg(&qsl[i + 1]) - __ldg(&qsl[i]);
                v = __ldg(&nct[__ldg(&idx_mapping[i])]) + qlen;
            }
            seq_out[i] = (float)v;
        }
        return;
    }

    // ---- pos blocks: one request per block ----
    const int start = __ldg(&qsl[r]);
    const int end   = __ldg(&qsl[r + 1]);
    const int im    = __ldg(&idx_mapping[r]);   // parallel with qsl loads
    if (end <= start) return;
    const int nv    = __ldg(&nct[im]);          // the one dependent load
    const int base  = nv - start;               // pos[t] = base + t

    const int aligned_s0 = (start + 3) & ~3;
    const int aligned_s1 = end & ~3;

    if (aligned_s1 > aligned_s0) {
        // head (<=3 elems)
        int t = start + (int)threadIdx.x;
        if (t < aligned_s0) out_base[t] = (float)(base + t);

        // vector body: per-thread stream of float4 stores, values advanced
        // by packed f32x2 adds (+1024.0 per component per iteration)
        const int nvec = (aligned_s1 - aligned_s0) >> 2;
        float4* vout = reinterpret_cast<float4*>(out_base + aligned_s0);

        int v = (int)threadIdx.x;
        if (v < nvec) {
            int tv0 = aligned_s0 + (v << 2) + base;
            float f0 = (float)tv0;               // single I2F per thread
            unsigned long long lo = packf2(f0, f0 + 1.0f);
            unsigned long long hi = packf2(f0 + 2.0f, f0 + 3.0f);
            const unsigned long long inc = packf2(1024.0f, 1024.0f);
            do {
                *reinterpret_cast<ulonglong2*>(vout + v) =
                    make_ulonglong2(lo, hi);
                lo = addf32x2(lo, inc);
                hi = addf32x2(hi, inc);
                v += 256;
            } while (v < nvec);
        }

        // tail (<=3 elems)
        int tt = aligned_s1 + (int)threadIdx.x;
        if (tt < end) out_base[tt] = (float)(base + tt);
    } else {
        for (int t = start + (int)threadIdx.x; t < end; t += (int)blockDim.x)
            out_base[t] = (float)(base + t);
    }
}

extern "C" void kernel_launch(void* const* d_in, const int* in_sizes, int n_in,
                              void* d_out, int out_size) {
    // stable sort of input indices by size (ascending)
    int ord[32];
    int n = n_in > 32 ? 32 : n_in;
    for (int i = 0; i < n; i++) ord[i] = i;
    for (int i = 1; i < n; i++) {
        int key = ord[i];
        int j = i - 1;
        while (j >= 0 && in_sizes[ord[j]] > in_sizes[key]) {
            ord[j + 1] = ord[j];
            j--;
        }
        ord[j + 1] = key;
    }
    // rank mapping: ord[0]=idx_mapping, ord[1]=qsl, ord[2]=num_computed_tokens
    int idx_i = ord[0];
    int qsl_i = (n > 1) ? ord[1] : ord[0];
    int nct_i = (n > 2) ? ord[2] : qsl_i;

    const int* idx_mapping = (const int*)d_in[idx_i];
    const int* qsl         = (const int*)d_in[qsl_i];
    const int* nct         = (const int*)d_in[nct_i];

    // unit: size(qsl) - size(idx) == bytes-per-element of in_sizes
    long long unit = (long long)in_sizes[qsl_i] - (long long)in_sizes[idx_i];
    if (unit <= 0) unit = 1;
    const int num_reqs     = (int)(in_sizes[idx_i] / unit);
    const int max_num_reqs = (int)(in_sizes[nct_i] / unit);

    fused_fill_kernel<<<num_reqs + SEQ_BLOCKS, 256>>>(
        idx_mapping, qsl, nct, (float*)d_out,
        num_reqs, max_num_reqs, (long long)out_size);
}

// round 14
// speedup vs baseline: 1.2452x; 1.0019x over previous
#include <cuda_runtime.h>
#include <cstdint>

// Ragged position fill (vLLM prepare-inputs style), single fused kernel.
//   pos[t]      = nct[idx_mapping[req(t)]] + (t - qsl[req(t)])   (= base + t)
//   seq_lens[r] = nct[idx_mapping[r]] + (qsl[r+1]-qsl[r]) for r < num_reqs, else 0
// d_out = [ pos (num_tokens) | seq_lens (max_num_reqs) ]  as FLOAT32.
//
// FINAL: seven structurally different designs (65K/8K/4K/1.2K blocks, STG and
// TMA-bulk, default/.cs policy, balanced tiles, persistent+prefetch) all
// plateau at 16.6-17.0us = 67MB of stores at ~4 TB/s — the L2 store-path
// ceiling (store throughput ~= half the ~7-8 TB/s read-path LTS cap). With
// the output size fixed by the problem, this is the hardware roofline.
// This artifact (round 8/13, 16.58us ncu) is the simplest design on it:
// one block per request, f32x2-incremented STG.128 bodies, dedicated
// seq_lens blocks.

#define SEQ_BLOCKS 64

__device__ __forceinline__ unsigned long long addf32x2(unsigned long long a,
                                                       unsigned long long b) {
    unsigned long long r;
    asm("add.rn.f32x2 %0, %1, %2;" : "=l"(r) : "l"(a), "l"(b));
    return r;
}

__device__ __forceinline__ unsigned long long packf2(float lo, float hi) {
    unsigned long long r;
    asm("mov.b64 %0, {%1, %2};" : "=l"(r) : "f"(lo), "f"(hi));
    return r;
}

__global__ __launch_bounds__(256) void fused_fill_kernel(
    const int* __restrict__ idx_mapping,
    const int* __restrict__ qsl,
    const int* __restrict__ nct,
    float* __restrict__ out_base,
    int num_reqs, int max_num_reqs,
    long long out_size)
{
    const int r = blockIdx.x;

    if (r >= num_reqs) {
        // ---- seq_lens blocks: cover [0, max_num_reqs) ----
        const long long num_tokens = (long long)__ldg(&qsl[num_reqs]);
        const long long need = num_tokens + (long long)max_num_reqs;
        if (out_size != need && out_size != 4 * need) return;  // no room in d_out
        float* seq_out = out_base + num_tokens;

        const int nthreads = SEQ_BLOCKS * 256;
        int i = (r - num_reqs) * 256 + (int)threadIdx.x;
        for (; i < max_num_reqs; i += nthreads) {
            int v = 0;
            if (i < num_reqs) {
                int qlen = __ldg(&qsl[i + 1]) - __ldg(&qsl[i]);
                v = __ldg(&nct[__ldg(&idx_mapping[i])]) + qlen;
            }
            seq_out[i] = (float)v;
        }
        return;
    }

    // ---- pos blocks: one request per block ----
    const int start = __ldg(&qsl[r]);
    const int end   = __ldg(&qsl[r + 1]);
    const int im    = __ldg(&idx_mapping[r]);   // parallel with qsl loads
    if (end <= start) return;
    const int nv    = __ldg(&nct[im]);          // the one dependent load
    const int base  = nv - start;               // pos[t] = base + t

    const int aligned_s0 = (start + 3) & ~3;
    const int aligned_s1 = end & ~3;

    if (aligned_s1 > aligned_s0) {
        // head (<=3 elems)
        int t = start + (int)threadIdx.x;
        if (t < aligned_s0) out_base[t] = (float)(base + t);

        // vector body: per-thread stream of float4 stores, values advanced
        // by packed f32x2 adds (+1024.0 per component per iteration)
        const int nvec = (aligned_s1 - aligned_s0) >> 2;
        float4* vout = reinterpret_cast<float4*>(out_base + aligned_s0);

        int v = (int)threadIdx.x;
        if (v < nvec) {
            int tv0 = aligned_s0 + (v << 2) + base;
            float f0 = (float)tv0;               // single I2F per thread
            unsigned long long lo = packf2(f0, f0 + 1.0f);
            unsigned long long hi = packf2(f0 + 2.0f, f0 + 3.0f);
            const unsigned long long inc = packf2(1024.0f, 1024.0f);
            do {
                *reinterpret_cast<ulonglong2*>(vout + v) =
                    make_ulonglong2(lo, hi);
                lo = addf32x2(lo, inc);
                hi = addf32x2(hi, inc);
                v += 256;
            } while (v < nvec);
        }

        // tail (<=3 elems)
        int tt = aligned_s1 + (int)threadIdx.x;
        if (tt < end) out_base[tt] = (float)(base + tt);
    } else {
        for (int t = start + (int)threadIdx.x; t < end; t += (int)blockDim.x)
            out_base[t] = (float)(base + t);
    }
}

extern "C" void kernel_launch(void* const* d_in, const int* in_sizes, int n_in,
                              void* d_out, int out_size) {
    // stable sort of input indices by size (ascending)
    int ord[32];
    int n = n_in > 32 ? 32 : n_in;
    for (int i = 0; i < n; i++) ord[i] = i;
    for (int i = 1; i < n; i++) {
        int key = ord[i];
        int j = i - 1;
        while (j >= 0 && in_sizes[ord[j]] > in_sizes[key]) {
            ord[j + 1] = ord[j];
            j--;
        }
        ord[j + 1] = key;
    }
    // rank mapping: ord[0]=idx_mapping, ord[1]=qsl, ord[2]=num_computed_tokens
    int idx_i = ord[0];
    int qsl_i = (n > 1) ? ord[1] : ord[0];
    int nct_i = (n > 2) ? ord[2] : qsl_i;

    const int* idx_mapping = (const int*)d_in[idx_i];
    const int* qsl         = (const int*)d_in[qsl_i];
    const int* nct         = (const int*)d_in[nct_i];

    // unit: size(qsl) - size(idx) == bytes-per-element of in_sizes
    long long unit = (long long)in_sizes[qsl_i] - (long long)in_sizes[idx_i];
    if (unit <= 0) unit = 1;
    const int num_reqs     = (int)(in_sizes[idx_i] / unit);
    const int max_num_reqs = (int)(in_sizes[nct_i] / unit);

    fused_fill_kernel<<<num_reqs + SEQ_BLOCKS, 256>>>(
        idx_mapping, qsl, nct, (float*)d_out,
        num_reqs, max_num_reqs, (long long)out_size);
}

// round 15
// speedup vs baseline: 1.2718x; 1.0214x over previous
#include <cuda_runtime.h>
#include <cstdint>

// Ragged position fill (vLLM prepare-inputs style), single fused kernel.
//   pos[t]      = nct[idx_mapping[req(t)]] + (t - qsl[req(t)])   (= base + t)
//   seq_lens[r] = nct[idx_mapping[r]] + (qsl[r+1]-qsl[r]) for r < num_reqs, else 0
// d_out = [ pos (num_tokens) | seq_lens (max_num_reqs) ]  as FLOAT32.
//
// R15: all prior designs used 16B stores and tied at 16.6-17.0us with L1tex
// the top pipe — store *wavefront* count never varied. Blackwell adds 256-bit
// stores (st.global.v8.f32 -> STG.E.256); this halves store instructions and
// wavefronts at identical bytes. Decisive either way: faster => wavefront
// path was the binder; neutral => byte-path ceiling confirmed.

#define SEQ_BLOCKS 64

__device__ __forceinline__ unsigned long long addf32x2(unsigned long long a,
                                                       unsigned long long b) {
    unsigned long long r;
    asm("add.rn.f32x2 %0, %1, %2;" : "=l"(r) : "l"(a), "l"(b));
    return r;
}

__device__ __forceinline__ unsigned long long packf2(float lo, float hi) {
    unsigned long long r;
    asm("mov.b64 %0, {%1, %2};" : "=l"(r) : "f"(lo), "f"(hi));
    return r;
}

// 256-bit store of 4 packed f32x2 register pairs (sm_100+ / Blackwell)
__device__ __forceinline__ void stg_v8(float* p,
                                       unsigned long long p0,
                                       unsigned long long p1,
                                       unsigned long long p2,
                                       unsigned long long p3) {
    float2 a = *reinterpret_cast<float2*>(&p0);
    float2 b = *reinterpret_cast<float2*>(&p1);
    float2 c = *reinterpret_cast<float2*>(&p2);
    float2 d = *reinterpret_cast<float2*>(&p3);
    asm volatile(
        "st.global.v8.f32 [%0], {%1, %2, %3, %4, %5, %6, %7, %8};"
        :: "l"(p), "f"(a.x), "f"(a.y), "f"(b.x), "f"(b.y),
           "f"(c.x), "f"(c.y), "f"(d.x), "f"(d.y)
        : "memory");
}

__global__ __launch_bounds__(256) void fused_fill_kernel(
    const int* __restrict__ idx_mapping,
    const int* __restrict__ qsl,
    const int* __restrict__ nct,
    float* __restrict__ out_base,
    int num_reqs, int max_num_reqs,
    long long out_size)
{
    const int r = blockIdx.x;

    if (r >= num_reqs) {
        // ---- seq_lens blocks: cover [0, max_num_reqs) ----
        const long long num_tokens = (long long)__ldg(&qsl[num_reqs]);
        const long long need = num_tokens + (long long)max_num_reqs;
        if (out_size != need && out_size != 4 * need) return;  // no room in d_out
        float* seq_out = out_base + num_tokens;

        const int nthreads = SEQ_BLOCKS * 256;
        int i = (r - num_reqs) * 256 + (int)threadIdx.x;
        for (; i < max_num_reqs; i += nthreads) {
            int v = 0;
            if (i < num_reqs) {
                int qlen = __ldg(&qsl[i + 1]) - __ldg(&qsl[i]);
                v = __ldg(&nct[__ldg(&idx_mapping[i])]) + qlen;
            }
            seq_out[i] = (float)v;
        }
        return;
    }

    // ---- pos blocks: one request per block ----
    const int start = __ldg(&qsl[r]);
    const int end   = __ldg(&qsl[r + 1]);
    const int im    = __ldg(&idx_mapping[r]);   // parallel with qsl loads
    if (end <= start) return;
    const int nv    = __ldg(&nct[im]);          // the one dependent load
    const int base  = nv - start;               // pos[t] = base + t

    // body aligned to 8 floats (32B) for STG.256
    const int a0 = (start + 7) & ~7;
    const int a1 = end & ~7;

    if (a1 > a0) {
        // head (<=7 elems)
        int t = start + (int)threadIdx.x;
        if (t < a0) out_base[t] = (float)(base + t);

        // vector body: per-thread stream of 32B stores; values advanced by
        // packed f32x2 adds (+2048.0 per component per iteration; exact)
        const int nvec = (a1 - a0) >> 3;       // number of 8-float groups
        int v = (int)threadIdx.x;
        if (v < nvec) {
            float f0 = (float)(a0 + (v << 3) + base);   // single I2F
            unsigned long long p0 = packf2(f0,        f0 + 1.0f);
            unsigned long long p1 = packf2(f0 + 2.0f, f0 + 3.0f);
            unsigned long long p2 = packf2(f0 + 4.0f, f0 + 5.0f);
            unsigned long long p3 = packf2(f0 + 6.0f, f0 + 7.0f);
            const unsigned long long inc = packf2(2048.0f, 2048.0f);
            do {
                stg_v8(out_base + a0 + (v << 3), p0, p1, p2, p3);
                p0 = addf32x2(p0, inc);
                p1 = addf32x2(p1, inc);
                p2 = addf32x2(p2, inc);
                p3 = addf32x2(p3, inc);
                v += 256;
            } while (v < nvec);
        }

        // tail (<=7 elems)
        int tt = a1 + (int)threadIdx.x;
        if (tt < end) out_base[tt] = (float)(base + tt);
    } else {
        for (int t = start + (int)threadIdx.x; t < end; t += (int)blockDim.x)
            out_base[t] = (float)(base + t);
    }
}

extern "C" void kernel_launch(void* const* d_in, const int* in_sizes, int n_in,
                              void* d_out, int out_size) {
    // stable sort of input indices by size (ascending)
    int ord[32];
    int n = n_in > 32 ? 32 : n_in;
    for (int i = 0; i < n; i++) ord[i] = i;
    for (int i = 1; i < n; i++) {
        int key = ord[i];
        int j = i - 1;
        while (j >= 0 && in_sizes[ord[j]] > in_sizes[key]) {
            ord[j + 1] = ord[j];
            j--;
        }
        ord[j + 1] = key;
    }
    // rank mapping: ord[0]=idx_mapping, ord[1]=qsl, ord[2]=num_computed_tokens
    int idx_i = ord[0];
    int qsl_i = (n > 1) ? ord[1] : ord[0];
    int nct_i = (n > 2) ? ord[2] : qsl_i;

    const int* idx_mapping = (const int*)d_in[idx_i];
    const int* qsl         = (const int*)d_in[qsl_i];
    const int* nct         = (const int*)d_in[nct_i];

    // unit: size(qsl) - size(idx) == bytes-per-element of in_sizes
    long long unit = (long long)in_sizes[qsl_i] - (long long)in_sizes[idx_i];
    if (unit <= 0) unit = 1;
    const int num_reqs     = (int)(in_sizes[idx_i] / unit);
    const int max_num_reqs = (int)(in_sizes[nct_i] / unit);

    fused_fill_kernel<<<num_reqs + SEQ_BLOCKS, 256>>>(
        idx_mapping, qsl, nct, (float*)d_out,
        num_reqs, max_num_reqs, (long long)out_size);
}

// round 16
// speedup vs baseline: 1.4116x; 1.1099x over previous
#include <cuda_runtime.h>
#include <cstdint>

// Ragged position fill (vLLM prepare-inputs style), single fused kernel.
//   pos[t]      = nct[idx_mapping[req(t)]] + (t - qsl[req(t)])   (= base + t)
//   seq_lens[r] = nct[idx_mapping[r]] + (qsl[r+1]-qsl[r]) for r < num_reqs, else 0
// d_out = [ pos (num_tokens) | seq_lens (max_num_reqs) ]  as FLOAT32.
//
// R16: R15 (STG.256) is best at 16.45us. This round halves block size to 128
// threads: ~2x resident CTAs (3.5 waves instead of 7), so twice as many
// independent qsl/idx->nct prologue chains overlap — attacking the residual
// latency component the STG.256 delta proved exists. Payload path unchanged:
// per-thread STG.256 stream advanced by packed f32x2 adds.

#define SEQ_BLOCKS 64
#define BLK 128

__device__ __forceinline__ unsigned long long addf32x2(unsigned long long a,
                                                       unsigned long long b) {
    unsigned long long r;
    asm("add.rn.f32x2 %0, %1, %2;" : "=l"(r) : "l"(a), "l"(b));
    return r;
}

__device__ __forceinline__ unsigned long long packf2(float lo, float hi) {
    unsigned long long r;
    asm("mov.b64 %0, {%1, %2};" : "=l"(r) : "f"(lo), "f"(hi));
    return r;
}

// 256-bit store of 4 packed f32x2 register pairs (sm_100+ / Blackwell)
__device__ __forceinline__ void stg_v8(float* p,
                                       unsigned long long p0,
                                       unsigned long long p1,
                                       unsigned long long p2,
                                       unsigned long long p3) {
    float2 a = *reinterpret_cast<float2*>(&p0);
    float2 b = *reinterpret_cast<float2*>(&p1);
    float2 c = *reinterpret_cast<float2*>(&p2);
    float2 d = *reinterpret_cast<float2*>(&p3);
    asm volatile(
        "st.global.v8.f32 [%0], {%1, %2, %3, %4, %5, %6, %7, %8};"
        :: "l"(p), "f"(a.x), "f"(a.y), "f"(b.x), "f"(b.y),
           "f"(c.x), "f"(c.y), "f"(d.x), "f"(d.y)
        : "memory");
}

__global__ __launch_bounds__(BLK) void fused_fill_kernel(
    const int* __restrict__ idx_mapping,
    const int* __restrict__ qsl,
    const int* __restrict__ nct,
    float* __restrict__ out_base,
    int num_reqs, int max_num_reqs,
    long long out_size)
{
    const int r = blockIdx.x;

    if (r >= num_reqs) {
        // ---- seq_lens blocks: cover [0, max_num_reqs) ----
        const long long num_tokens = (long long)__ldg(&qsl[num_reqs]);
        const long long need = num_tokens + (long long)max_num_reqs;
        if (out_size != need && out_size != 4 * need) return;  // no room in d_out
        float* seq_out = out_base + num_tokens;

        const int nthreads = SEQ_BLOCKS * BLK;
        int i = (r - num_reqs) * BLK + (int)threadIdx.x;
        for (; i < max_num_reqs; i += nthreads) {
            int v = 0;
            if (i < num_reqs) {
                int qlen = __ldg(&qsl[i + 1]) - __ldg(&qsl[i]);
                v = __ldg(&nct[__ldg(&idx_mapping[i])]) + qlen;
            }
            seq_out[i] = (float)v;
        }
        return;
    }

    // ---- pos blocks: one request per block ----
    const int start = __ldg(&qsl[r]);
    const int end   = __ldg(&qsl[r + 1]);
    const int im    = __ldg(&idx_mapping[r]);   // parallel with qsl loads
    if (end <= start) return;
    const int nv    = __ldg(&nct[im]);          // the one dependent load
    const int base  = nv - start;               // pos[t] = base + t

    // body aligned to 8 floats (32B) for STG.256
    const int a0 = (start + 7) & ~7;
    const int a1 = end & ~7;

    if (a1 > a0) {
        // head (<=7 elems)
        int t = start + (int)threadIdx.x;
        if (t < a0) out_base[t] = (float)(base + t);

        // vector body: per-thread stream of 32B stores; values advanced by
        // packed f32x2 adds (+BLK*8 per component per iteration; fp32-exact)
        const int nvec = (a1 - a0) >> 3;       // number of 8-float groups
        int v = (int)threadIdx.x;
        if (v < nvec) {
            float f0 = (float)(a0 + (v << 3) + base);   // single I2F
            unsigned long long p0 = packf2(f0,        f0 + 1.0f);
            unsigned long long p1 = packf2(f0 + 2.0f, f0 + 3.0f);
            unsigned long long p2 = packf2(f0 + 4.0f, f0 + 5.0f);
            unsigned long long p3 = packf2(f0 + 6.0f, f0 + 7.0f);
            const unsigned long long inc =
                packf2((float)(BLK * 8), (float)(BLK * 8));
            do {
                stg_v8(out_base + a0 + (v << 3), p0, p1, p2, p3);
                p0 = addf32x2(p0, inc);
                p1 = addf32x2(p1, inc);
                p2 = addf32x2(p2, inc);
                p3 = addf32x2(p3, inc);
                v += BLK;
            } while (v < nvec);
        }

        // tail (<=7 elems)
        int tt = a1 + (int)threadIdx.x;
        if (tt < end) out_base[tt] = (float)(base + tt);
    } else {
        for (int t = start + (int)threadIdx.x; t < end; t += BLK)
            out_base[t] = (float)(base + t);
    }
}

extern "C" void kernel_launch(void* const* d_in, const int* in_sizes, int n_in,
                              void* d_out, int out_size) {
    // stable sort of input indices by size (ascending)
    int ord[32];
    int n = n_in > 32 ? 32 : n_in;
    for (int i = 0; i < n; i++) ord[i] = i;
    for (int i = 1; i < n; i++) {
        int key = ord[i];
        int j = i - 1;
        while (j >= 0 && in_sizes[ord[j]] > in_sizes[key]) {
            ord[j + 1] = ord[j];
            j--;
        }
        ord[j + 1] = key;
    }
    // rank mapping: ord[0]=idx_mapping, ord[1]=qsl, ord[2]=num_computed_tokens
    int idx_i = ord[0];
    int qsl_i = (n > 1) ? ord[1] : ord[0];
    int nct_i = (n > 2) ? ord[2] : qsl_i;

    const int* idx_mapping = (const int*)d_in[idx_i];
    const int* qsl         = (const int*)d_in[qsl_i];
    const int* nct         = (const int*)d_in[nct_i];

    // unit: size(qsl) - size(idx) == bytes-per-element of in_sizes
    long long unit = (long long)in_sizes[qsl_i] - (long long)in_sizes[idx_i];
    if (unit <= 0) unit = 1;
    const int num_reqs     = (int)(in_sizes[idx_i] / unit);
    const int max_num_reqs = (int)(in_sizes[nct_i] / unit);

    fused_fill_kernel<<<num_reqs + SEQ_BLOCKS, BLK>>>(
        idx_mapping, qsl, nct, (float*)d_out,
        num_reqs, max_num_reqs, (long long)out_size);
}